// round 3
// baseline (speedup 1.0000x reference)
#include <cuda_runtime.h>
#include <math.h>

// Problem dimensions (fixed by setup_inputs)
#define NS 150   // spatial training points
#define NT 40    // temporal training points
#define MS 200   // spatial test points
#define MT 30    // temporal test points
#define PRS 160  // padded rows (spatial), multiple of 32
#define PRT 64   // padded rows (temporal)
#define JITTER 0.1f

#define EIG_SMEM ((PRS*NS + 512) * 4)

// -------- scratch (device globals; no allocation allowed) --------
__device__ float g_ws[NS], g_wt[NT];
__device__ float g_Vs[NS*NS];   // col-major: g_Vs[col*NS + row]
__device__ float g_VsT[NS*NS];  // row-major: g_VsT[row*NS + col]
__device__ float g_Vt[NT*NT];   // col-major
__device__ float g_VtT[NT*NT];  // row-major
__device__ float g_T1[NS*NT], g_T2[NS*NT], g_T3[NS*NT], g_Amat[NS*NT];
__device__ float g_D[NS*NT];
__device__ float g_Ts[MS*NS], g_Tt[MT*NT];
__device__ float g_P1[MS*NT];
__device__ float g_Cs[MS*NS], g_Ct[MT*NT];
__device__ float g_Q1[MS*NT];

// ---------------- one-sided parallel Jacobi ----------------
// A: smem, col-major with PR padded rows (pad rows are zero and stay zero).
// For symmetric PSD A, orthogonalizing columns gives col_i -> lambda_i * v_i.
template<int N, int PR, int R>
__device__ void jacobi_onesided(float* A, int tid, int lane, int wid, int* conv)
{
    const int NP = N / 2;
    const int NR = N - 1;
    for (int sweep = 0; sweep < 20; ++sweep) {
        if (tid == 0) *conv = 0;
        __syncthreads();
        float offmax = 0.f;
        for (int round = 0; round < NR; ++round) {
            for (int pair = wid; pair < NP; pair += 32) {
                int p, q;
                if (pair == 0) { p = N - 1; q = round; }
                else {
                    p = (round + pair) % NR;
                    q = (round - pair + NR) % NR;
                }
                float* colp = A + p * PR;
                float* colq = A + q * PR;
                float ap[R], aq[R];
                float app = 0.f, aqq = 0.f, apq = 0.f;
                #pragma unroll
                for (int k = 0; k < R; ++k) {
                    int r = lane + 32 * k;
                    ap[k] = colp[r];
                    aq[k] = colq[r];
                    app = fmaf(ap[k], ap[k], app);
                    aqq = fmaf(aq[k], aq[k], aqq);
                    apq = fmaf(ap[k], aq[k], apq);
                }
                #pragma unroll
                for (int o = 16; o; o >>= 1) {
                    app += __shfl_xor_sync(0xffffffffu, app, o);
                    aqq += __shfl_xor_sync(0xffffffffu, aqq, o);
                    apq += __shfl_xor_sync(0xffffffffu, apq, o);
                }
                float rel = (apq * apq) / (app * aqq);
                offmax = fmaxf(offmax, rel);
                if (rel > 1e-14f) {
                    float tau = (aqq - app) / (2.f * apq);
                    float t = copysignf(1.f, tau) / (fabsf(tau) + sqrtf(fmaf(tau, tau, 1.f)));
                    float c = rsqrtf(fmaf(t, t, 1.f));
                    float s = c * t;
                    #pragma unroll
                    for (int k = 0; k < R; ++k) {
                        int r = lane + 32 * k;
                        colp[r] = fmaf(c, ap[k], -s * aq[k]);
                        colq[r] = fmaf(s, ap[k],  c * aq[k]);
                    }
                }
            }
            __syncthreads();
        }
        // sweep convergence check (warp-reduced max, then one atomic per warp)
        #pragma unroll
        for (int o = 16; o; o >>= 1)
            offmax = fmaxf(offmax, __shfl_xor_sync(0xffffffffu, offmax, o));
        if (lane == 0) atomicMax(conv, __float_as_int(offmax));
        __syncthreads();
        float mx = __int_as_float(*conv);
        __syncthreads();
        if (mx < 1e-11f) break;
    }
}

template<int N, int PR, int R>
__device__ void extract_eig(const float* A, float* wOut, float* Vcm, float* Vrm,
                            int lane, int wid)
{
    for (int col = wid; col < N; col += 32) {
        float a[R]; float s2 = 0.f;
        #pragma unroll
        for (int k = 0; k < R; ++k) {
            int r = lane + 32 * k;
            a[k] = A[col * PR + r];
            s2 = fmaf(a[k], a[k], s2);
        }
        #pragma unroll
        for (int o = 16; o; o >>= 1)
            s2 += __shfl_xor_sync(0xffffffffu, s2, o);
        float nrm = sqrtf(s2);            // = eigenvalue (PSD, jitter => > 0)
        if (lane == 0) wOut[col] = nrm;
        float inv = 1.f / nrm;
        #pragma unroll
        for (int k = 0; k < R; ++k) {
            int r = lane + 32 * k;
            if (r < N) {
                float v = a[k] * inv;
                Vcm[col * N + r] = v;
                Vrm[r * N + col] = v;
            }
        }
    }
}

// block 0: spatial 150x150; block 1: temporal 40x40
__global__ void __launch_bounds__(1024, 1)
eig_kernel(const float* __restrict__ space, const float* __restrict__ timec,
           const float* __restrict__ lll, const float* __restrict__ lle,
           const float* __restrict__ llt)
{
    extern __shared__ float sm[];
    __shared__ int conv;
    const int tid = threadIdx.x, lane = tid & 31, wid = tid >> 5;

    if (blockIdx.x == 0) {
        float* A = sm;                 // PRS x NS col-major
        float* C = sm + PRS * NS;      // coords (450)
        for (int i = tid; i < NS * 3; i += blockDim.x) C[i] = space[i];
        __syncthreads();
        float ll = expf(lll[0]), le = expf(lle[0]);
        float il2 = 1.f / (ll * ll), ie2 = 1.f / (le * le);
        for (int e = tid; e < NS * NS; e += blockDim.x) {
            int i = e % NS, j = e / NS;
            float dx = C[i*3+0] - C[j*3+0];
            float dy = C[i*3+1] - C[j*3+1];
            float dz = C[i*3+2] - C[j*3+2];
            float v = expf(-((dx*dx + dy*dy) * il2 + dz*dz * ie2));
            if (i == j) v += JITTER;
            A[j * PRS + i] = v;
        }
        for (int e = tid; e < NS * (PRS - NS); e += blockDim.x) {
            int j = e / (PRS - NS);
            int r = NS + e % (PRS - NS);
            A[j * PRS + r] = 0.f;
        }
        __syncthreads();
        jacobi_onesided<NS, PRS, 5>(A, tid, lane, wid, &conv);
        extract_eig<NS, PRS, 5>(A, g_ws, g_Vs, g_VsT, lane, wid);
    } else {
        float* A = sm;                 // PRT x NT col-major
        float* C = sm + PRT * NT;      // 40 time coords
        for (int i = tid; i < NT; i += blockDim.x) C[i] = timec[i];
        __syncthreads();
        float lt = expf(llt[0]);
        float it2 = 1.f / (lt * lt);
        for (int e = tid; e < NT * NT; e += blockDim.x) {
            int i = e % NT, j = e / NT;
            float d = C[i] - C[j];
            float v = expf(-d * d * it2);
            if (i == j) v += JITTER;
            A[j * PRT + i] = v;
        }
        for (int e = tid; e < NT * (PRT - NT); e += blockDim.x) {
            int j = e / (PRT - NT);
            int r = NT + e % (PRT - NT);
            A[j * PRT + r] = 0.f;
        }
        __syncthreads();
        jacobi_onesided<NT, PRT, 2>(A, tid, lane, wid, &conv);
        extract_eig<NT, PRT, 2>(A, g_wt, g_Vt, g_VtT, lane, wid);
    }
}

// ---------------- test-kernel construction ----------------
__global__ void build_test_kernel(const float* __restrict__ tsp, const float* __restrict__ sp,
                                  const float* __restrict__ tti, const float* __restrict__ ti,
                                  const float* __restrict__ lll, const float* __restrict__ lle,
                                  const float* __restrict__ llt)
{
    int idx = blockIdx.x * blockDim.x + threadIdx.x;
    if (idx < MS * NS) {
        float ll = expf(lll[0]), le = expf(lle[0]);
        float il2 = 1.f / (ll * ll), ie2 = 1.f / (le * le);
        int m = idx / NS, i = idx % NS;
        float dx = tsp[m*3+0] - sp[i*3+0];
        float dy = tsp[m*3+1] - sp[i*3+1];
        float dz = tsp[m*3+2] - sp[i*3+2];
        g_Ts[idx] = expf(-((dx*dx + dy*dy) * il2 + dz*dz * ie2));
    } else if (idx < MS * NS + MT * NT) {
        int k = idx - MS * NS;
        int u = k / NT, t = k % NT;
        float lt = expf(llt[0]);
        float it2 = 1.f / (lt * lt);
        float d = tti[u] - ti[t];
        g_Tt[k] = expf(-d * d * it2);
    }
}

// ---------------- alpha path: A = Vs (D .* (Vs^T S Vt)) Vt^T ----------------
__global__ void t1_kernel(const float* __restrict__ S) {
    int idx = blockIdx.x * blockDim.x + threadIdx.x;
    if (idx >= NS * NT) return;
    int j = idx / NT, t = idx % NT;
    float acc = 0.f;
    for (int i = 0; i < NS; ++i)
        acc = fmaf(g_Vs[j * NS + i], S[i * NT + t], acc);
    g_T1[idx] = acc;
}

__global__ void t2_kernel(const float* __restrict__ lnv) {
    int idx = blockIdx.x * blockDim.x + threadIdx.x;
    if (idx >= NS * NT) return;
    int j = idx / NT, u = idx % NT;
    float acc = 0.f;
    for (int t = 0; t < NT; ++t)
        acc = fmaf(g_T1[j * NT + t], g_Vt[u * NT + t], acc);
    float vn = expf(lnv[0]);
    float d = 1.f / fmaf(g_ws[j], g_wt[u], vn);
    g_D[idx] = d;
    g_T2[idx] = acc * d;
}

__global__ void t3_kernel() {
    int idx = blockIdx.x * blockDim.x + threadIdx.x;
    if (idx >= NS * NT) return;
    int i = idx / NT, u = idx % NT;
    float acc = 0.f;
    for (int j = 0; j < NS; ++j)
        acc = fmaf(g_VsT[i * NS + j], g_T2[j * NT + u], acc);
    g_T3[idx] = acc;
}

__global__ void amat_kernel() {
    int idx = blockIdx.x * blockDim.x + threadIdx.x;
    if (idx >= NS * NT) return;
    int i = idx / NT, t = idx % NT;
    float acc = 0.f;
    for (int u = 0; u < NT; ++u)
        acc = fmaf(g_T3[i * NT + u], g_Vt[u * NT + t], acc);
    g_Amat[idx] = acc;
}

// ---------------- prediction path ----------------
__global__ void p1_kernel() {
    int idx = blockIdx.x * blockDim.x + threadIdx.x;
    if (idx >= MS * NT) return;
    int m = idx / NT, t = idx % NT;
    float acc = 0.f;
    for (int i = 0; i < NS; ++i)
        acc = fmaf(g_Ts[m * NS + i], g_Amat[i * NT + t], acc);
    g_P1[idx] = acc;
}

__global__ void pred_kernel(float* __restrict__ out) {
    int idx = blockIdx.x * blockDim.x + threadIdx.x;
    if (idx >= MS * MT) return;
    int m = idx / MT, u = idx % MT;
    float acc = 0.f;
    for (int t = 0; t < NT; ++t)
        acc = fmaf(g_P1[m * NT + t], g_Tt[u * NT + t], acc);
    out[idx] = acc;   // yPred[m, u], row-major [MS, MT]
}

// ---------------- variance path ----------------
__global__ void csct_kernel() {
    int idx = blockIdx.x * blockDim.x + threadIdx.x;
    if (idx < MS * NS) {
        int m = idx / NS, j = idx % NS;
        float acc = 0.f;
        for (int i = 0; i < NS; ++i)
            acc = fmaf(g_Ts[m * NS + i], g_VsT[i * NS + j], acc);
        g_Cs[idx] = acc * acc;
    } else if (idx < MS * NS + MT * NT) {
        int k = idx - MS * NS;
        int u = k / NT, v = k % NT;
        float acc = 0.f;
        for (int t = 0; t < NT; ++t)
            acc = fmaf(g_Tt[u * NT + t], g_VtT[t * NT + v], acc);
        g_Ct[k] = acc * acc;
    }
}

__global__ void q1_kernel() {
    int idx = blockIdx.x * blockDim.x + threadIdx.x;
    if (idx >= MS * NT) return;
    int m = idx / NT, v = idx % NT;
    float acc = 0.f;
    for (int j = 0; j < NS; ++j)
        acc = fmaf(g_Cs[m * NS + j], g_D[j * NT + v], acc);
    g_Q1[idx] = acc;
}

__global__ void var_kernel(float* __restrict__ out, const float* __restrict__ lsv) {
    int idx = blockIdx.x * blockDim.x + threadIdx.x;
    if (idx >= MS * MT) return;
    int m = idx / MT, u = idx % MT;
    float acc = 0.f;
    for (int v = 0; v < NT; ++v)
        acc = fmaf(g_Q1[m * NT + v], g_Ct[u * NT + v], acc);
    out[MS * MT + idx] = expf(lsv[0]) - acc;   // yVar[m, u]
}

// ---------------- launch ----------------
extern "C" void kernel_launch(void* const* d_in, const int* in_sizes, int n_in,
                              void* d_out, int out_size)
{
    const float* space  = (const float*)d_in[0];
    const float* timec  = (const float*)d_in[1];
    const float* stData = (const float*)d_in[2];
    const float* tspace = (const float*)d_in[3];
    const float* ttime  = (const float*)d_in[4];
    const float* l_ll   = (const float*)d_in[5];
    const float* l_le   = (const float*)d_in[6];
    const float* l_lt   = (const float*)d_in[7];
    const float* l_nv   = (const float*)d_in[8];
    const float* l_sv   = (const float*)d_in[9];
    float* out = (float*)d_out;

    cudaFuncSetAttribute(eig_kernel, cudaFuncAttributeMaxDynamicSharedMemorySize, EIG_SMEM);

    eig_kernel<<<2, 1024, EIG_SMEM>>>(space, timec, l_ll, l_le, l_lt);

    {   // test kernels (independent of eigen, but stream-serial is fine)
        int n = MS * NS + MT * NT;
        build_test_kernel<<<(n + 255) / 256, 256>>>(tspace, space, ttime, timec,
                                                    l_ll, l_le, l_lt);
    }

    t1_kernel<<<(NS * NT + 255) / 256, 256>>>(stData);
    t2_kernel<<<(NS * NT + 255) / 256, 256>>>(l_nv);
    t3_kernel<<<(NS * NT + 255) / 256, 256>>>();
    amat_kernel<<<(NS * NT + 255) / 256, 256>>>();

    {   // Cs / Ct (squared eigen-projections of test kernels)
        int n = MS * NS + MT * NT;
        csct_kernel<<<(n + 255) / 256, 256>>>();
    }

    p1_kernel<<<(MS * NT + 255) / 256, 256>>>();
    pred_kernel<<<(MS * MT + 255) / 256, 256>>>(out);

    q1_kernel<<<(MS * NT + 255) / 256, 256>>>();
    var_kernel<<<(MS * MT + 255) / 256, 256>>>(out, l_sv);
}

// round 9
// speedup vs baseline: 1.0692x; 1.0692x over previous
#include <cuda_runtime.h>
#include <math.h>

// Problem dimensions (fixed by setup_inputs)
#define NS 150   // spatial training points
#define NT 40    // temporal training points
#define MS 200   // spatial test points
#define MT 30    // temporal test points
#define PRS 160  // padded rows (spatial), multiple of 32
#define PRT 64   // padded rows (temporal)
#define JITTER 0.1f

#define EIG_THREADS 800          // 25 warps
#define EIG_SMEM ((PRS*NS + 512) * 4)

// -------- scratch (device globals; no allocation allowed) --------
__device__ float g_ws[NS], g_wt[NT];
__device__ float g_Vs[NS*NS];   // col-major: g_Vs[col*NS + row]
__device__ float g_VsT[NS*NS];  // row-major: g_VsT[row*NS + col]
__device__ float g_Vt[NT*NT];   // col-major
__device__ float g_VtT[NT*NT];  // row-major
__device__ float g_T1[NS*NT], g_T2[NS*NT], g_T3[NS*NT], g_Amat[NS*NT];
__device__ float g_D[NS*NT];
__device__ float g_Ts[MS*NS], g_Tt[MT*NT];
__device__ float g_P1[MS*NT];
__device__ float g_Cs[MS*NS], g_Ct[MT*NT];
__device__ float g_Q1[MS*NT];

__device__ __forceinline__ float warp_sum(float v) {
    #pragma unroll
    for (int o = 16; o; o >>= 1) v += __shfl_xor_sync(0xffffffffu, v, o);
    return v;
}
__device__ __forceinline__ float warp_max(float v) {
    #pragma unroll
    for (int o = 16; o; o >>= 1) v = fmaxf(v, __shfl_xor_sync(0xffffffffu, v, o));
    return v;
}

// ---------------- one-sided parallel Jacobi ----------------
// A: smem, col-major with PR padded rows (pad rows zero, stay zero).
// For symmetric PSD A, orthogonalizing columns gives col_i -> lambda_i * v_i.
// B pairs per warp, fully interleaved for ILP. Requires (N/2) % B == 0.
template<int N, int PR, int R, int B>
__device__ void jacobi_onesided(float* A, int tid, int lane, int wid, int* conv)
{
    const int NP = N / 2;
    const int NR = N - 1;
    const int NW = NP / B;           // warps doing work
    for (int sweep = 0; sweep < 18; ++sweep) {
        if (tid == 0) *conv = 0;
        __syncthreads();
        float offmax = 0.f;
        for (int round = 0; round < NR; ++round) {
            if (wid < NW) {
                float ap[B][R], aq[B][R];
                float app[B], aqq[B], apq[B];
                float *cp[B], *cq[B];
                #pragma unroll
                for (int b = 0; b < B; ++b) {
                    int pair = wid * B + b;
                    int p, q;
                    if (pair == 0) { p = N - 1; q = round; }
                    else {
                        p = (round + pair) % NR;
                        q = (round - pair + NR) % NR;
                    }
                    cp[b] = A + p * PR;
                    cq[b] = A + q * PR;
                    #pragma unroll
                    for (int k = 0; k < R; ++k) {
                        int r = lane + 32 * k;
                        ap[b][k] = cp[b][r];
                        aq[b][k] = cq[b][r];
                    }
                }
                #pragma unroll
                for (int b = 0; b < B; ++b) {
                    app[b] = 0.f; aqq[b] = 0.f; apq[b] = 0.f;
                    #pragma unroll
                    for (int k = 0; k < R; ++k) {
                        app[b] = fmaf(ap[b][k], ap[b][k], app[b]);
                        aqq[b] = fmaf(aq[b][k], aq[b][k], aqq[b]);
                        apq[b] = fmaf(ap[b][k], aq[b][k], apq[b]);
                    }
                }
                // butterfly reduction, level-interleaved across B pairs:
                // 3*B independent SHFLs per level -> throughput-bound, latency hidden
                #pragma unroll
                for (int o = 16; o; o >>= 1) {
                    #pragma unroll
                    for (int b = 0; b < B; ++b) {
                        app[b] += __shfl_xor_sync(0xffffffffu, app[b], o);
                        aqq[b] += __shfl_xor_sync(0xffffffffu, aqq[b], o);
                        apq[b] += __shfl_xor_sync(0xffffffffu, apq[b], o);
                    }
                }
                #pragma unroll
                for (int b = 0; b < B; ++b) {
                    float rel = (apq[b] * apq[b]) / (app[b] * aqq[b]);
                    offmax = fmaxf(offmax, rel);
                    if (rel > 1e-13f) {
                        float tau = (aqq[b] - app[b]) / (2.f * apq[b]);
                        float t = copysignf(1.f, tau) / (fabsf(tau) + sqrtf(fmaf(tau, tau, 1.f)));
                        float c = rsqrtf(fmaf(t, t, 1.f));
                        float s = c * t;
                        #pragma unroll
                        for (int k = 0; k < R; ++k) {
                            int r = lane + 32 * k;
                            cp[b][r] = fmaf(c, ap[b][k], -s * aq[b][k]);
                            cq[b][r] = fmaf(s, ap[b][k],  c * aq[b][k]);
                        }
                    }
                }
            }
            __syncthreads();
        }
        // sweep convergence check
        offmax = warp_max(offmax);
        if (lane == 0) atomicMax(conv, __float_as_int(offmax));
        __syncthreads();
        float mx = __int_as_float(*conv);
        __syncthreads();
        if (mx < 1e-10f) break;
    }
}

template<int N, int PR, int R>
__device__ void extract_eig(const float* A, float* wOut, float* Vcm, float* Vrm,
                            int lane, int wid, int nwarps)
{
    for (int col = wid; col < N; col += nwarps) {
        float a[R]; float s2 = 0.f;
        #pragma unroll
        for (int k = 0; k < R; ++k) {
            int r = lane + 32 * k;
            a[k] = A[col * PR + r];
            s2 = fmaf(a[k], a[k], s2);
        }
        s2 = warp_sum(s2);
        float nrm = sqrtf(s2);            // = eigenvalue (PSD, jitter => > 0)
        if (lane == 0) wOut[col] = nrm;
        float inv = 1.f / nrm;
        #pragma unroll
        for (int k = 0; k < R; ++k) {
            int r = lane + 32 * k;
            if (r < N) {
                float v = a[k] * inv;
                Vcm[col * N + r] = v;
                Vrm[r * N + col] = v;
            }
        }
    }
}

// block 0: spatial 150x150; block 1: temporal 40x40
__global__ void __launch_bounds__(EIG_THREADS, 1)
eig_kernel(const float* __restrict__ space, const float* __restrict__ timec,
           const float* __restrict__ lll, const float* __restrict__ lle,
           const float* __restrict__ llt)
{
    extern __shared__ float sm[];
    __shared__ int conv;
    const int tid = threadIdx.x, lane = tid & 31, wid = tid >> 5;
    const int nwarps = EIG_THREADS >> 5;

    if (blockIdx.x == 0) {
        float* A = sm;                 // PRS x NS col-major
        float* C = sm + PRS * NS;      // coords (450)
        for (int i = tid; i < NS * 3; i += blockDim.x) C[i] = space[i];
        __syncthreads();
        float ll = expf(lll[0]), le = expf(lle[0]);
        float il2 = 1.f / (ll * ll), ie2 = 1.f / (le * le);
        for (int e = tid; e < NS * NS; e += blockDim.x) {
            int i = e % NS, j = e / NS;
            float dx = C[i*3+0] - C[j*3+0];
            float dy = C[i*3+1] - C[j*3+1];
            float dz = C[i*3+2] - C[j*3+2];
            float v = expf(-((dx*dx + dy*dy) * il2 + dz*dz * ie2));
            if (i == j) v += JITTER;
            A[j * PRS + i] = v;
        }
        for (int e = tid; e < NS * (PRS - NS); e += blockDim.x) {
            int j = e / (PRS - NS);
            int r = NS + e % (PRS - NS);
            A[j * PRS + r] = 0.f;
        }
        __syncthreads();
        jacobi_onesided<NS, PRS, 5, 3>(A, tid, lane, wid, &conv);  // 25 warps x 3 pairs
        extract_eig<NS, PRS, 5>(A, g_ws, g_Vs, g_VsT, lane, wid, nwarps);
    } else {
        float* A = sm;                 // PRT x NT col-major
        float* C = sm + PRT * NT;      // 40 time coords
        for (int i = tid; i < NT; i += blockDim.x) C[i] = timec[i];
        __syncthreads();
        float lt = expf(llt[0]);
        float it2 = 1.f / (lt * lt);
        for (int e = tid; e < NT * NT; e += blockDim.x) {
            int i = e % NT, j = e / NT;
            float d = C[i] - C[j];
            float v = expf(-d * d * it2);
            if (i == j) v += JITTER;
            A[j * PRT + i] = v;
        }
        for (int e = tid; e < NT * (PRT - NT); e += blockDim.x) {
            int j = e / (PRT - NT);
            int r = NT + e % (PRT - NT);
            A[j * PRT + r] = 0.f;
        }
        __syncthreads();
        jacobi_onesided<NT, PRT, 2, 2>(A, tid, lane, wid, &conv);  // 10 warps x 2 pairs
        extract_eig<NT, PRT, 2>(A, g_wt, g_Vt, g_VtT, lane, wid, nwarps);
    }
}

// ---------------- test-kernel construction ----------------
__global__ void build_test_kernel(const float* __restrict__ tsp, const float* __restrict__ sp,
                                  const float* __restrict__ tti, const float* __restrict__ ti,
                                  const float* __restrict__ lll, const float* __restrict__ lle,
                                  const float* __restrict__ llt)
{
    int idx = blockIdx.x * blockDim.x + threadIdx.x;
    if (idx < MS * NS) {
        float ll = expf(lll[0]), le = expf(lle[0]);
        float il2 = 1.f / (ll * ll), ie2 = 1.f / (le * le);
        int m = idx / NS, i = idx % NS;
        float dx = tsp[m*3+0] - sp[i*3+0];
        float dy = tsp[m*3+1] - sp[i*3+1];
        float dz = tsp[m*3+2] - sp[i*3+2];
        g_Ts[idx] = expf(-((dx*dx + dy*dy) * il2 + dz*dz * ie2));
    } else if (idx < MS * NS + MT * NT) {
        int k = idx - MS * NS;
        int u = k / NT, t = k % NT;
        float lt = expf(llt[0]);
        float it2 = 1.f / (lt * lt);
        float d = tti[u] - ti[t];
        g_Tt[k] = expf(-d * d * it2);
    }
}

// ---------------- alpha path: A = Vs (D .* (Vs^T S Vt)) Vt^T ----------------
__global__ void t1_kernel(const float* __restrict__ S) {
    int idx = blockIdx.x * blockDim.x + threadIdx.x;
    if (idx >= NS * NT) return;
    int j = idx / NT, t = idx % NT;
    float acc = 0.f;
    for (int i = 0; i < NS; ++i)
        acc = fmaf(g_Vs[j * NS + i], S[i * NT + t], acc);
    g_T1[idx] = acc;
}

__global__ void t2_kernel(const float* __restrict__ lnv) {
    int idx = blockIdx.x * blockDim.x + threadIdx.x;
    if (idx >= NS * NT) return;
    int j = idx / NT, u = idx % NT;
    float acc = 0.f;
    for (int t = 0; t < NT; ++t)
        acc = fmaf(g_T1[j * NT + t], g_Vt[u * NT + t], acc);
    float vn = expf(lnv[0]);
    float d = 1.f / fmaf(g_ws[j], g_wt[u], vn);
    g_D[idx] = d;
    g_T2[idx] = acc * d;
}

__global__ void t3_kernel() {
    int idx = blockIdx.x * blockDim.x + threadIdx.x;
    if (idx >= NS * NT) return;
    int i = idx / NT, u = idx % NT;
    float acc = 0.f;
    for (int j = 0; j < NS; ++j)
        acc = fmaf(g_VsT[i * NS + j], g_T2[j * NT + u], acc);
    g_T3[idx] = acc;
}

__global__ void amat_kernel() {
    int idx = blockIdx.x * blockDim.x + threadIdx.x;
    if (idx >= NS * NT) return;
    int i = idx / NT, t = idx % NT;
    float acc = 0.f;
    for (int u = 0; u < NT; ++u)
        acc = fmaf(g_T3[i * NT + u], g_Vt[u * NT + t], acc);
    g_Amat[idx] = acc;
}

// ---------------- prediction path ----------------
__global__ void p1_kernel() {
    int idx = blockIdx.x * blockDim.x + threadIdx.x;
    if (idx >= MS * NT) return;
    int m = idx / NT, t = idx % NT;
    float acc = 0.f;
    for (int i = 0; i < NS; ++i)
        acc = fmaf(g_Ts[m * NS + i], g_Amat[i * NT + t], acc);
    g_P1[idx] = acc;
}

__global__ void pred_kernel(float* __restrict__ out) {
    int idx = blockIdx.x * blockDim.x + threadIdx.x;
    if (idx >= MS * MT) return;
    int m = idx / MT, u = idx % MT;
    float acc = 0.f;
    for (int t = 0; t < NT; ++t)
        acc = fmaf(g_P1[m * NT + t], g_Tt[u * NT + t], acc);
    out[idx] = acc;   // yPred[m, u], row-major [MS, MT]
}

// ---------------- variance path ----------------
__global__ void csct_kernel() {
    int idx = blockIdx.x * blockDim.x + threadIdx.x;
    if (idx < MS * NS) {
        int m = idx / NS, j = idx % NS;
        float acc = 0.f;
        for (int i = 0; i < NS; ++i)
            acc = fmaf(g_Ts[m * NS + i], g_VsT[i * NS + j], acc);
        g_Cs[idx] = acc * acc;
    } else if (idx < MS * NS + MT * NT) {
        int k = idx - MS * NS;
        int u = k / NT, v = k % NT;
        float acc = 0.f;
        for (int t = 0; t < NT; ++t)
            acc = fmaf(g_Tt[u * NT + t], g_VtT[t * NT + v], acc);
        g_Ct[k] = acc * acc;
    }
}

__global__ void q1_kernel() {
    int idx = blockIdx.x * blockDim.x + threadIdx.x;
    if (idx >= MS * NT) return;
    int m = idx / NT, v = idx % NT;
    float acc = 0.f;
    for (int j = 0; j < NS; ++j)
        acc = fmaf(g_Cs[m * NS + j], g_D[j * NT + v], acc);
    g_Q1[idx] = acc;
}

__global__ void var_kernel(float* __restrict__ out, const float* __restrict__ lsv) {
    int idx = blockIdx.x * blockDim.x + threadIdx.x;
    if (idx >= MS * MT) return;
    int m = idx / MT, u = idx % MT;
    float acc = 0.f;
    for (int v = 0; v < NT; ++v)
        acc = fmaf(g_Q1[m * NT + v], g_Ct[u * NT + v], acc);
    out[MS * MT + idx] = expf(lsv[0]) - acc;   // yVar[m, u]
}

// ---------------- launch ----------------
extern "C" void kernel_launch(void* const* d_in, const int* in_sizes, int n_in,
                              void* d_out, int out_size)
{
    const float* space  = (const float*)d_in[0];
    const float* timec  = (const float*)d_in[1];
    const float* stData = (const float*)d_in[2];
    const float* tspace = (const float*)d_in[3];
    const float* ttime  = (const float*)d_in[4];
    const float* l_ll   = (const float*)d_in[5];
    const float* l_le   = (const float*)d_in[6];
    const float* l_lt   = (const float*)d_in[7];
    const float* l_nv   = (const float*)d_in[8];
    const float* l_sv   = (const float*)d_in[9];
    float* out = (float*)d_out;

    cudaFuncSetAttribute(eig_kernel, cudaFuncAttributeMaxDynamicSharedMemorySize, EIG_SMEM);

    eig_kernel<<<2, EIG_THREADS, EIG_SMEM>>>(space, timec, l_ll, l_le, l_lt);

    {   // test kernels (independent of eigen)
        int n = MS * NS + MT * NT;
        build_test_kernel<<<(n + 255) / 256, 256>>>(tspace, space, ttime, timec,
                                                    l_ll, l_le, l_lt);
    }

    t1_kernel<<<(NS * NT + 255) / 256, 256>>>(stData);
    t2_kernel<<<(NS * NT + 255) / 256, 256>>>(l_nv);
    t3_kernel<<<(NS * NT + 255) / 256, 256>>>();
    amat_kernel<<<(NS * NT + 255) / 256, 256>>>();

    {   // Cs / Ct (squared eigen-projections of test kernels)
        int n = MS * NS + MT * NT;
        csct_kernel<<<(n + 255) / 256, 256>>>();
    }

    p1_kernel<<<(MS * NT + 255) / 256, 256>>>();
    pred_kernel<<<(MS * MT + 255) / 256, 256>>>(out);

    q1_kernel<<<(MS * NT + 255) / 256, 256>>>();
    var_kernel<<<(MS * MT + 255) / 256, 256>>>(out, l_sv);
}